// round 1
// baseline (speedup 1.0000x reference)
#include <cuda_runtime.h>
#include <math.h>

#define N 8192
#define D 768
#define INV_T 20.0f
#define DIAG_PEN 1.0e12f
#define EPSN 1e-8f

#define BM 64
#define BN 64
#define BK 16
#define NSPLIT 4
#define JT_PER_SPLIT ((N / BN) / NSPLIT)   // 32 j-tiles per split
#define RED_BLOCKS (N / 256)               // 32

// Scratch (no cudaMalloc allowed)
__device__ float g_xn[N * D];              // normalized rows, fp32
__device__ float g_mpart[NSPLIT][N];
__device__ float g_spart[NSPLIT][N];
__device__ float g_t[N];                   // logits[i, i^1]
__device__ float g_partial[RED_BLOCKS];

// ---------------------------------------------------------------------------
// Kernel 1: row L2 norms + normalize
// ---------------------------------------------------------------------------
__global__ void normalize_kernel(const float* __restrict__ x) {
    int row = blockIdx.x;
    int tid = threadIdx.x;
    __shared__ float red[8];

    float ss = 0.0f;
    #pragma unroll
    for (int c = tid; c < D; c += 256) {
        float v = x[row * D + c];
        ss = fmaf(v, v, ss);
    }
    #pragma unroll
    for (int o = 16; o; o >>= 1) ss += __shfl_down_sync(0xffffffffu, ss, o);
    if ((tid & 31) == 0) red[tid >> 5] = ss;
    __syncthreads();
    if (tid < 8) {
        float v = red[tid];
        #pragma unroll
        for (int o = 4; o; o >>= 1) v += __shfl_down_sync(0xffu, v, o);
        if (tid == 0) red[0] = v;
    }
    __syncthreads();
    float inv = 1.0f / fmaxf(sqrtf(red[0]), EPSN);
    #pragma unroll
    for (int c = tid; c < D; c += 256) {
        g_xn[row * D + c] = x[row * D + c] * inv;
    }
}

// ---------------------------------------------------------------------------
// Kernel 2: fused sim-GEMM + online log-sum-exp per row (per column split)
// grid = (N/BM, NSPLIT), block = 256 (16x16 threads, 4x4 micro-tile)
// ---------------------------------------------------------------------------
__global__ void __launch_bounds__(256) simloss_kernel() {
    const int rt    = blockIdx.x;          // row tile
    const int split = blockIdx.y;
    const int r0    = rt * BM;
    const int tid   = threadIdx.x;
    const int tx    = tid & 15;
    const int ty    = tid >> 4;

    __shared__ float As[BK][BM];
    __shared__ float Bs[BK][BN];
    __shared__ float red[BM][16];
    __shared__ float tilem[BM];
    __shared__ float runm[BM];
    __shared__ float runs[BM];

    if (tid < BM) { runm[tid] = -INFINITY; runs[tid] = 0.0f; }
    // runm/runs only ever touched by thread `tid` itself -> no sync needed.

    const int ldrow = tid >> 2;            // 0..63
    const int ldk4  = (tid & 3) * 4;       // 0,4,8,12

    for (int jt = 0; jt < JT_PER_SPLIT; ++jt) {
        const int j0 = (split * JT_PER_SPLIT + jt) * BN;
        float acc[4][4] = {};

        for (int k0 = 0; k0 < D; k0 += BK) {
            float4 av = *(const float4*)&g_xn[(r0 + ldrow) * D + k0 + ldk4];
            float4 bv = *(const float4*)&g_xn[(j0 + ldrow) * D + k0 + ldk4];
            __syncthreads();               // prior compute / reduction done
            As[ldk4 + 0][ldrow] = av.x;
            As[ldk4 + 1][ldrow] = av.y;
            As[ldk4 + 2][ldrow] = av.z;
            As[ldk4 + 3][ldrow] = av.w;
            Bs[ldk4 + 0][ldrow] = bv.x;
            Bs[ldk4 + 1][ldrow] = bv.y;
            Bs[ldk4 + 2][ldrow] = bv.z;
            Bs[ldk4 + 3][ldrow] = bv.w;
            __syncthreads();
            #pragma unroll
            for (int k = 0; k < BK; ++k) {
                float4 a = *(const float4*)&As[k][ty * 4];
                float4 b = *(const float4*)&Bs[k][tx * 4];
                acc[0][0] = fmaf(a.x, b.x, acc[0][0]);
                acc[0][1] = fmaf(a.x, b.y, acc[0][1]);
                acc[0][2] = fmaf(a.x, b.z, acc[0][2]);
                acc[0][3] = fmaf(a.x, b.w, acc[0][3]);
                acc[1][0] = fmaf(a.y, b.x, acc[1][0]);
                acc[1][1] = fmaf(a.y, b.y, acc[1][1]);
                acc[1][2] = fmaf(a.y, b.z, acc[1][2]);
                acc[1][3] = fmaf(a.y, b.w, acc[1][3]);
                acc[2][0] = fmaf(a.z, b.x, acc[2][0]);
                acc[2][1] = fmaf(a.z, b.y, acc[2][1]);
                acc[2][2] = fmaf(a.z, b.z, acc[2][2]);
                acc[2][3] = fmaf(a.z, b.w, acc[2][3]);
                acc[3][0] = fmaf(a.w, b.x, acc[3][0]);
                acc[3][1] = fmaf(a.w, b.y, acc[3][1]);
                acc[3][2] = fmaf(a.w, b.z, acc[3][2]);
                acc[3][3] = fmaf(a.w, b.w, acc[3][3]);
            }
        }
        __syncthreads();                   // As/Bs done; red[] free to reuse

        // logits, diag mask, label capture, local max of 4 cols
        #pragma unroll
        for (int r = 0; r < 4; ++r) {
            const int gi = r0 + ty * 4 + r;
            float mx = -INFINITY;
            #pragma unroll
            for (int c = 0; c < 4; ++c) {
                const int gj = j0 + tx * 4 + c;
                float l = acc[r][c] * INV_T;
                if (gi == gj) l -= DIAG_PEN * INV_T;
                if (gj == (gi ^ 1)) g_t[gi] = l;
                acc[r][c] = l;
                mx = fmaxf(mx, l);
            }
            red[ty * 4 + r][tx] = mx;
        }
        __syncthreads();
        if (tid < BM) {
            float mx = -INFINITY;
            #pragma unroll
            for (int q = 0; q < 16; ++q) mx = fmaxf(mx, red[tid][q]);
            tilem[tid] = mx;
        }
        __syncthreads();
        #pragma unroll
        for (int r = 0; r < 4; ++r) {
            const float mx = tilem[ty * 4 + r];
            float s = 0.0f;
            #pragma unroll
            for (int c = 0; c < 4; ++c) s += expf(acc[r][c] - mx);
            red[ty * 4 + r][tx] = s;
        }
        __syncthreads();
        if (tid < BM) {
            float s = 0.0f;
            #pragma unroll
            for (int q = 0; q < 16; ++q) s += red[tid][q];
            const float mo = runm[tid];
            const float mt = tilem[tid];
            const float mn = fmaxf(mo, mt);
            runs[tid] = runs[tid] * expf(mo - mn) + s * expf(mt - mn);
            runm[tid] = mn;
        }
        __syncthreads();                   // red[] reuse next iteration
    }

    if (tid < BM) {
        g_mpart[split][r0 + tid] = runm[tid];
        g_spart[split][r0 + tid] = runs[tid];
    }
}

// ---------------------------------------------------------------------------
// Kernel 3: merge splits per row, per-block deterministic partial sums
// ---------------------------------------------------------------------------
__global__ void reduce_rows_kernel() {
    const int row = blockIdx.x * 256 + threadIdx.x;
    __shared__ float red[8];

    float M = -INFINITY;
    #pragma unroll
    for (int s = 0; s < NSPLIT; ++s) M = fmaxf(M, g_mpart[s][row]);
    float S = 0.0f;
    #pragma unroll
    for (int s = 0; s < NSPLIT; ++s) S += g_spart[s][row] * expf(g_mpart[s][row] - M);
    float li = (M + logf(S)) - g_t[row];

    #pragma unroll
    for (int o = 16; o; o >>= 1) li += __shfl_down_sync(0xffffffffu, li, o);
    if ((threadIdx.x & 31) == 0) red[threadIdx.x >> 5] = li;
    __syncthreads();
    if (threadIdx.x < 8) {
        float v = red[threadIdx.x];
        #pragma unroll
        for (int o = 4; o; o >>= 1) v += __shfl_down_sync(0xffu, v, o);
        if (threadIdx.x == 0) g_partial[blockIdx.x] = v;
    }
}

// ---------------------------------------------------------------------------
// Kernel 4: final deterministic sum -> mean -> d_out[0]
// ---------------------------------------------------------------------------
__global__ void final_kernel(float* __restrict__ out) {
    float v = g_partial[threadIdx.x];
    #pragma unroll
    for (int o = 16; o; o >>= 1) v += __shfl_down_sync(0xffffffffu, v, o);
    if (threadIdx.x == 0) out[0] = v * (1.0f / (float)N);
}

extern "C" void kernel_launch(void* const* d_in, const int* in_sizes, int n_in,
                              void* d_out, int out_size) {
    const float* x = (const float*)d_in[0];
    float* out = (float*)d_out;

    normalize_kernel<<<N, 256>>>(x);
    dim3 grid(N / BM, NSPLIT);
    simloss_kernel<<<grid, 256>>>();
    reduce_rows_kernel<<<RED_BLOCKS, 256>>>();
    final_kernel<<<1, 32>>>(out);
}

// round 4
// speedup vs baseline: 8.0419x; 8.0419x over previous
#include <cuda_runtime.h>
#include <cuda_bf16.h>
#include <cstdint>
#include <math.h>

#define N 8192
#define D 768
#define INV_T 20.0f
#define DIAG_SUB 2.0e13f      /* 1e12 * 20 */
#define EPSN 1e-8f

#define BM 128
#define BN 128
#define SPLIT 8
#define JT 8                   /* j-tiles per CTA: 64 / SPLIT */
#define BK 32                  /* K per B chunk */
#define NKC (D / BK)           /* 24 chunks per j-tile */
#define RED_BLOCKS (N / 256)   /* 32 */

#define AST 1552               /* A smem row stride bytes (1536 + 16) */
#define BST 80                 /* B smem row stride bytes (64 + 16) */
#define A_BYTES (BM * AST)     /* 198656 */
#define B_BYTES (BM * BST)     /* 10240 per buffer */
#define SMEM_DYN (A_BYTES + 2 * B_BYTES)   /* 219136 */

// ---------------------------------------------------------------------------
// device scratch (no cudaMalloc allowed)
// ---------------------------------------------------------------------------
__device__ __nv_bfloat16 g_xnb[N * D];
__device__ float g_mpart[SPLIT][N];
__device__ float g_spart[SPLIT][N];
__device__ float g_t[N];
__device__ float g_partial[RED_BLOCKS];

// ---------------------------------------------------------------------------
// PTX helpers (baseline PTX only — no sm_103a-specific features)
// ---------------------------------------------------------------------------
__device__ __forceinline__ void cp_async16(uint32_t saddr, const void* gptr) {
    asm volatile("cp.async.cg.shared.global [%0], [%1], 16;"
                 :: "r"(saddr), "l"(__cvta_generic_to_global(gptr)) : "memory");
}
#define CP_COMMIT() asm volatile("cp.async.commit_group;" ::: "memory")
#define CP_WAIT(n)  asm volatile("cp.async.wait_group %0;" :: "n"(n) : "memory")

__device__ __forceinline__ void ldsm_x4(uint32_t* r, uint32_t addr) {
    asm volatile("ldmatrix.sync.aligned.m8n8.x4.shared.b16 {%0,%1,%2,%3}, [%4];"
                 : "=r"(r[0]), "=r"(r[1]), "=r"(r[2]), "=r"(r[3]) : "r"(addr));
}

__device__ __forceinline__ void mma_bf16(float* d, const uint32_t* a,
                                         uint32_t b0, uint32_t b1) {
    asm volatile(
        "mma.sync.aligned.m16n8k16.row.col.f32.bf16.bf16.f32 "
        "{%0,%1,%2,%3}, {%4,%5,%6,%7}, {%8,%9}, {%0,%1,%2,%3};"
        : "+f"(d[0]), "+f"(d[1]), "+f"(d[2]), "+f"(d[3])
        : "r"(a[0]), "r"(a[1]), "r"(a[2]), "r"(a[3]), "r"(b0), "r"(b1));
}

// ---------------------------------------------------------------------------
// Kernel 1: row L2 norms + normalize -> bf16
// ---------------------------------------------------------------------------
__global__ void normalize_kernel(const float* __restrict__ x) {
    int row = blockIdx.x;
    int tid = threadIdx.x;
    __shared__ float red[8];

    float ss = 0.0f;
    #pragma unroll
    for (int c = tid; c < D; c += 256) {
        float v = x[row * D + c];
        ss = fmaf(v, v, ss);
    }
    #pragma unroll
    for (int o = 16; o; o >>= 1) ss += __shfl_down_sync(0xffffffffu, ss, o);
    if ((tid & 31) == 0) red[tid >> 5] = ss;
    __syncthreads();
    if (tid < 8) {
        float v = red[tid];
        #pragma unroll
        for (int o = 4; o; o >>= 1) v += __shfl_down_sync(0xffu, v, o);
        if (tid == 0) red[0] = v;
    }
    __syncthreads();
    float inv = 1.0f / fmaxf(sqrtf(red[0]), EPSN);
    #pragma unroll
    for (int c = tid; c < D; c += 256) {
        g_xnb[row * D + c] = __float2bfloat16(x[row * D + c] * inv);
    }
}

// ---------------------------------------------------------------------------
// Kernel 2: bf16 mma.sync sim-GEMM + fused online LSE
// grid = (64, SPLIT), block = 512 (16 warps, 4x4; warp tile 32x32)
// A tile (128x768 bf16) resident in SMEM; B streamed 32-K chunks, cp.async x2.
// ---------------------------------------------------------------------------
__global__ void __launch_bounds__(512, 1) simloss_kernel() {
    extern __shared__ __align__(16) char smem[];
    char* const smA = smem;

    const int tid   = threadIdx.x;
    const int lane  = tid & 31;
    const int w     = tid >> 5;
    const int wm    = w & 3;          // warp row  (32 rows)
    const int wn    = w >> 2;         // warp col  (32 cols)
    const int rt    = blockIdx.x;
    const int split = blockIdx.y;
    const int r0    = rt * BM;

    const uint32_t sA = (uint32_t)__cvta_generic_to_shared(smA);
    const uint32_t sB0 = sA + A_BYTES;

    // ---- A tile load via cp.async: 128 rows x 1536B ----
    {
        #pragma unroll
        for (int it = 0; it < 24; ++it) {
            int idx = tid + it * 512;           // 0..12287
            int row = idx / 96;
            int u   = idx % 96;
            cp_async16(sA + row * AST + u * 16,
                       (const char*)g_xnb + (size_t)(r0 + row) * (D * 2) + u * 16);
        }
        CP_COMMIT();
    }

    // B chunk issue helper (each thread copies one 16B slot)
    const int brow  = tid >> 2;        // 0..127
    const int bslot = tid & 3;         // 0..3 (16B each = 64B row)

    // prologue: j-tile 0, chunks 0 and 1
    {
        const int j0 = (split * JT + 0) * BN;
        cp_async16(sB0 + brow * BST + bslot * 16,
                   (const char*)g_xnb + (size_t)(j0 + brow) * (D * 2) + 0 * 64 + bslot * 16);
        CP_COMMIT();
        cp_async16(sB0 + B_BYTES + brow * BST + bslot * 16,
                   (const char*)g_xnb + (size_t)(j0 + brow) * (D * 2) + 1 * 64 + bslot * 16);
        CP_COMMIT();
    }

    // per-thread fragment addresses
    const uint32_t aAddrBase = sA + (wm * 32 + (lane & 15)) * AST + (lane >> 4) * 16;
    const uint32_t bRowOff   = (wn * 32 + (lane & 15)) * BST + (lane >> 4) * 16;

    const int i_base    = r0 + wm * 32 + (lane >> 2);
    const int jcol_base = wn * 32 + (lane & 3) * 2;

    float rm[2][2], rs[2][2];
    #pragma unroll
    for (int a = 0; a < 2; ++a)
        #pragma unroll
        for (int b = 0; b < 2; ++b) { rm[a][b] = -INFINITY; rs[a][b] = 0.0f; }

    for (int jt = 0; jt < JT; ++jt) {
        const int j0 = (split * JT + jt) * BN;
        float acc[2][4][4];
        #pragma unroll
        for (int mt = 0; mt < 2; ++mt)
            #pragma unroll
            for (int nt = 0; nt < 4; ++nt)
                #pragma unroll
                for (int c = 0; c < 4; ++c) acc[mt][nt][c] = 0.0f;

        for (int kc = 0; kc < NKC; ++kc) {
            if (jt == JT - 1 && kc == NKC - 1) { CP_WAIT(0); } else { CP_WAIT(1); }
            __syncthreads();

            const uint32_t sB = sB0 + (kc & 1) * B_BYTES;
            #pragma unroll
            for (int ks = 0; ks < 2; ++ks) {
                uint32_t af[2][4], bf[2][4];
                #pragma unroll
                for (int mt = 0; mt < 2; ++mt)
                    ldsm_x4(af[mt], aAddrBase + mt * 16 * AST + kc * 64 + ks * 32);
                #pragma unroll
                for (int g = 0; g < 2; ++g)
                    ldsm_x4(bf[g], sB + bRowOff + g * 16 * BST + ks * 32);
                #pragma unroll
                for (int mt = 0; mt < 2; ++mt)
                    #pragma unroll
                    for (int nt = 0; nt < 4; ++nt) {
                        const int g = nt >> 1, hi = nt & 1;
                        mma_bf16(acc[mt][nt], af[mt], bf[g][hi], bf[g][hi + 2]);
                    }
            }
            __syncthreads();

            // prefetch chunk kc+2 (possibly into next j-tile)
            int nc = kc + 2;
            int njt = jt;
            if (nc >= NKC) { nc -= NKC; ++njt; }
            if (njt < JT) {
                const int nj0 = (split * JT + njt) * BN;
                cp_async16(sB0 + (nc & 1) * B_BYTES + brow * BST + bslot * 16,
                           (const char*)g_xnb + (size_t)(nj0 + brow) * (D * 2)
                               + nc * 64 + bslot * 16);
                CP_COMMIT();
            } else {
                CP_COMMIT();   // keep group counts aligned
            }
        }

        // ---- epilogue: scale, mask, label, online LSE (registers only) ----
        #pragma unroll
        for (int mt = 0; mt < 2; ++mt)
            #pragma unroll
            for (int rh = 0; rh < 2; ++rh) {
                const int i = i_base + mt * 16 + rh * 8;
                float v[8];
                float mx = -INFINITY;
                #pragma unroll
                for (int nt = 0; nt < 4; ++nt)
                    #pragma unroll
                    for (int cp = 0; cp < 2; ++cp) {
                        const int j = j0 + jcol_base + nt * 8 + cp;
                        float f = acc[mt][nt][rh * 2 + cp] * INV_T;
                        if (j == i) f -= DIAG_SUB;
                        if (j == (i ^ 1)) g_t[i] = f;
                        v[nt * 2 + cp] = f;
                        mx = fmaxf(mx, f);
                    }
                const float nm = fmaxf(rm[mt][rh], mx);
                float s = 0.0f;
                #pragma unroll
                for (int q = 0; q < 8; ++q) s += __expf(v[q] - nm);
                rs[mt][rh] = rs[mt][rh] * __expf(rm[mt][rh] - nm) + s;
                rm[mt][rh] = nm;
            }
    }

    // ---- merge (m,s): first across the 4 lanes sharing a row, then across
    //      the 4 warp-columns (wn) via SMEM. GEMM smem is dead by now. ----
    __syncthreads();                       // all cp.async drained, smem reusable
    float* bufm = (float*)smem;            // [4][BM]
    float* bufs = bufm + 4 * BM;           // [4][BM]

    #pragma unroll
    for (int mt = 0; mt < 2; ++mt)
        #pragma unroll
        for (int rh = 0; rh < 2; ++rh) {
            float m = rm[mt][rh], s = rs[mt][rh];
            #pragma unroll
            for (int off = 1; off <= 2; off <<= 1) {
                float mo = __shfl_xor_sync(0xffffffffu, m, off);
                float so = __shfl_xor_sync(0xffffffffu, s, off);
                float mn = fmaxf(m, mo);
                s = s * __expf(m - mn) + so * __expf(mo - mn);
                m = mn;
            }
            if ((lane & 3) == 0) {
                const int rl = wm * 32 + (lane >> 2) + mt * 16 + rh * 8;
                bufm[wn * BM + rl] = m;
                bufs[wn * BM + rl] = s;
            }
        }
    __syncthreads();

    if (tid < BM) {
        float M = -INFINITY;
        #pragma unroll
        for (int q = 0; q < 4; ++q) M = fmaxf(M, bufm[q * BM + tid]);
        float S = 0.0f;
        #pragma unroll
        for (int q = 0; q < 4; ++q) S += bufs[q * BM + tid] * __expf(bufm[q * BM + tid] - M);
        g_mpart[split][r0 + tid] = M;
        g_spart[split][r0 + tid] = S;
    }
}

// ---------------------------------------------------------------------------
// Kernel 3: merge splits per row, per-block deterministic partial sums
// ---------------------------------------------------------------------------
__global__ void reduce_rows_kernel() {
    const int row = blockIdx.x * 256 + threadIdx.x;
    __shared__ float red[8];

    float M = -INFINITY;
    #pragma unroll
    for (int s = 0; s < SPLIT; ++s) M = fmaxf(M, g_mpart[s][row]);
    float S = 0.0f;
    #pragma unroll
    for (int s = 0; s < SPLIT; ++s) S += g_spart[s][row] * __expf(g_mpart[s][row] - M);
    float li = (M + logf(S)) - g_t[row];

    #pragma unroll
    for (int o = 16; o; o >>= 1) li += __shfl_down_sync(0xffffffffu, li, o);
    if ((threadIdx.x & 31) == 0) red[threadIdx.x >> 5] = li;
    __syncthreads();
    if (threadIdx.x < 8) {
        float v = red[threadIdx.x];
        #pragma unroll
        for (int o = 4; o; o >>= 1) v += __shfl_down_sync(0xffu, v, o);
        if (threadIdx.x == 0) g_partial[blockIdx.x] = v;
    }
}

// ---------------------------------------------------------------------------
// Kernel 4: final deterministic sum -> mean
// ---------------------------------------------------------------------------
__global__ void final_kernel(float* __restrict__ out) {
    float v = g_partial[threadIdx.x];
    #pragma unroll
    for (int o = 16; o; o >>= 1) v += __shfl_down_sync(0xffffffffu, v, o);
    if (threadIdx.x == 0) out[0] = v * (1.0f / (float)N);
}

extern "C" void kernel_launch(void* const* d_in, const int* in_sizes, int n_in,
                              void* d_out, int out_size) {
    const float* x = (const float*)d_in[0];
    float* out = (float*)d_out;

    cudaFuncSetAttribute(simloss_kernel,
                         cudaFuncAttributeMaxDynamicSharedMemorySize, SMEM_DYN);

    normalize_kernel<<<N, 256>>>(x);
    dim3 grid(N / BM, SPLIT);
    simloss_kernel<<<grid, 512, SMEM_DYN>>>();
    reduce_rows_kernel<<<RED_BLOCKS, 256>>>();
    final_kernel<<<1, 32>>>(out);
}

// round 5
// speedup vs baseline: 8.9894x; 1.1178x over previous
#include <cuda_runtime.h>
#include <cuda_bf16.h>
#include <cstdint>
#include <math.h>

#define N 8192
#define D 768
#define INV_T 20.0f
#define DIAG_SUB 2.0e13f      /* 1e12 * 20 */
#define EPSN 1e-8f

#define BM 128
#define BN 128
#define SPLIT 16
#define JT 4                   /* j-tiles per CTA: 64 / SPLIT */
#define BK 32                  /* K per B chunk */
#define NKC (D / BK)           /* 24 chunks per j-tile */
#define NCH (JT * NKC)         /* 96 chunks per CTA */
#define RED_BLOCKS (N / 256)   /* 32 */

#define AST 1552               /* A smem row stride bytes (1536 + 16) */
#define BST 80                 /* B smem row stride bytes (64 + 16) */
#define A_BYTES (BM * AST)     /* 198656 */
#define B_BYTES (BM * BST)     /* 10240 per buffer */
#define SMEM_DYN (A_BYTES + 3 * B_BYTES)   /* 229376 <= 232448 */

// ---------------------------------------------------------------------------
// device scratch (no cudaMalloc allowed)
// ---------------------------------------------------------------------------
__device__ __nv_bfloat16 g_xnb[N * D];
__device__ float g_mpart[SPLIT][N];
__device__ float g_spart[SPLIT][N];
__device__ float g_t[N];
__device__ float g_partial[RED_BLOCKS];

// ---------------------------------------------------------------------------
// PTX helpers (baseline PTX only)
// ---------------------------------------------------------------------------
__device__ __forceinline__ void cp_async16(uint32_t saddr, const void* gptr) {
    asm volatile("cp.async.cg.shared.global [%0], [%1], 16;"
                 :: "r"(saddr), "l"(__cvta_generic_to_global(gptr)) : "memory");
}
#define CP_COMMIT() asm volatile("cp.async.commit_group;" ::: "memory")
#define CP_WAIT(n)  asm volatile("cp.async.wait_group %0;" :: "n"(n) : "memory")

__device__ __forceinline__ void ldsm_x4(uint32_t* r, uint32_t addr) {
    asm volatile("ldmatrix.sync.aligned.m8n8.x4.shared.b16 {%0,%1,%2,%3}, [%4];"
                 : "=r"(r[0]), "=r"(r[1]), "=r"(r[2]), "=r"(r[3]) : "r"(addr));
}

__device__ __forceinline__ void mma_bf16(float* d, const uint32_t* a,
                                         uint32_t b0, uint32_t b1) {
    asm volatile(
        "mma.sync.aligned.m16n8k16.row.col.f32.bf16.bf16.f32 "
        "{%0,%1,%2,%3}, {%4,%5,%6,%7}, {%8,%9}, {%0,%1,%2,%3};"
        : "+f"(d[0]), "+f"(d[1]), "+f"(d[2]), "+f"(d[3])
        : "r"(a[0]), "r"(a[1]), "r"(a[2]), "r"(a[3]), "r"(b0), "r"(b1));
}

// ---------------------------------------------------------------------------
// Kernel 1: row L2 norms + normalize -> bf16
// ---------------------------------------------------------------------------
__global__ void normalize_kernel(const float* __restrict__ x) {
    int row = blockIdx.x;
    int tid = threadIdx.x;
    __shared__ float red[8];

    float ss = 0.0f;
    #pragma unroll
    for (int c = tid; c < D; c += 256) {
        float v = x[row * D + c];
        ss = fmaf(v, v, ss);
    }
    #pragma unroll
    for (int o = 16; o; o >>= 1) ss += __shfl_down_sync(0xffffffffu, ss, o);
    if ((tid & 31) == 0) red[tid >> 5] = ss;
    __syncthreads();
    if (tid < 8) {
        float v = red[tid];
        #pragma unroll
        for (int o = 4; o; o >>= 1) v += __shfl_down_sync(0xffu, v, o);
        if (tid == 0) red[0] = v;
    }
    __syncthreads();
    float inv = 1.0f / fmaxf(sqrtf(red[0]), EPSN);
    #pragma unroll
    for (int c = tid; c < D; c += 256) {
        g_xnb[row * D + c] = __float2bfloat16(x[row * D + c] * inv);
    }
}

// ---------------------------------------------------------------------------
// Kernel 2: bf16 mma.sync sim-GEMM + fused online LSE
// grid = (64, SPLIT), block = 512 (16 warps 4x4; warp tile 32x32)
// A tile (128x768) SMEM-resident; B streamed BK=32 chunks, 3-stage cp.async
// ring with ONE __syncthreads per chunk.
// ---------------------------------------------------------------------------
__global__ void __launch_bounds__(512, 1) simloss_kernel() {
    extern __shared__ __align__(16) char smem[];

    const int tid   = threadIdx.x;
    const int lane  = tid & 31;
    const int w     = tid >> 5;
    const int wm    = w & 3;          // warp row  (32 rows)
    const int wn    = w >> 2;         // warp col  (32 cols)
    const int rt    = blockIdx.x;
    const int split = blockIdx.y;
    const int r0    = rt * BM;

    const uint32_t sA  = (uint32_t)__cvta_generic_to_shared(smem);
    const uint32_t sB0 = sA + A_BYTES;

    // ---- group 0: A tile (128 x 1536B) ----
    {
        #pragma unroll
        for (int it = 0; it < 24; ++it) {
            int idx = tid + it * 512;           // 0..12287
            int row = idx / 96;
            int u   = idx % 96;
            cp_async16(sA + row * AST + u * 16,
                       (const char*)g_xnb + (size_t)(r0 + row) * (D * 2) + u * 16);
        }
        CP_COMMIT();
    }

    const int brow  = tid >> 2;        // 0..127
    const int bslot = tid & 3;         // 16B slot

    // groups 1,2: chunks 0 and 1 (j-tile 0)
    {
        const int j0 = (split * JT) * BN;
        cp_async16(sB0 + 0 * B_BYTES + brow * BST + bslot * 16,
                   (const char*)g_xnb + (size_t)(j0 + brow) * (D * 2) + 0 * 64 + bslot * 16);
        CP_COMMIT();
        cp_async16(sB0 + 1 * B_BYTES + brow * BST + bslot * 16,
                   (const char*)g_xnb + (size_t)(j0 + brow) * (D * 2) + 1 * 64 + bslot * 16);
        CP_COMMIT();
    }

    const uint32_t aAddrBase = sA + (wm * 32 + (lane & 15)) * AST + (lane >> 4) * 16;
    const uint32_t bRowOff   = (wn * 32 + (lane & 15)) * BST + (lane >> 4) * 16;

    const int i_base    = r0 + wm * 32 + (lane >> 2);
    const int jcol_base = wn * 32 + (lane & 3) * 2;

    float rm[2][2], rs[2][2];
    #pragma unroll
    for (int a = 0; a < 2; ++a)
        #pragma unroll
        for (int b = 0; b < 2; ++b) { rm[a][b] = -INFINITY; rs[a][b] = 0.0f; }

    for (int jt = 0; jt < JT; ++jt) {
        const int j0 = (split * JT + jt) * BN;
        float acc[2][4][4];
        #pragma unroll
        for (int mt = 0; mt < 2; ++mt)
            #pragma unroll
            for (int nt = 0; nt < 4; ++nt)
                #pragma unroll
                for (int c = 0; c < 4; ++c) acc[mt][nt][c] = 0.0f;

        for (int kc = 0; kc < NKC; ++kc) {
            const int c = jt * NKC + kc;
            CP_WAIT(1);                 // chunk c arrived (c+1 may be in flight)
            __syncthreads();            // everyone done reading buf (c+2)%3

            // prefetch chunk c+2 into ring slot (c+2)%3
            {
                const int p = c + 2;
                if (p < NCH) {
                    const int pj0 = (split * JT + p / NKC) * BN;
                    const int pkc = p % NKC;
                    cp_async16(sB0 + (uint32_t)(p % 3) * B_BYTES + brow * BST + bslot * 16,
                               (const char*)g_xnb + (size_t)(pj0 + brow) * (D * 2)
                                   + pkc * 64 + bslot * 16);
                }
                CP_COMMIT();            // always commit to keep counts aligned
            }

            // batched fragment loads (fill LSU queue), then all MMAs
            const uint32_t sB = sB0 + (uint32_t)(c % 3) * B_BYTES;
            uint32_t af[2][2][4], bf[2][2][4];
            #pragma unroll
            for (int ks = 0; ks < 2; ++ks)
                #pragma unroll
                for (int mt = 0; mt < 2; ++mt)
                    ldsm_x4(af[ks][mt], aAddrBase + mt * 16 * AST + kc * 64 + ks * 32);
            #pragma unroll
            for (int ks = 0; ks < 2; ++ks)
                #pragma unroll
                for (int g = 0; g < 2; ++g)
                    ldsm_x4(bf[ks][g], sB + bRowOff + g * 16 * BST + ks * 32);

            #pragma unroll
            for (int ks = 0; ks < 2; ++ks)
                #pragma unroll
                for (int mt = 0; mt < 2; ++mt)
                    #pragma unroll
                    for (int nt = 0; nt < 4; ++nt) {
                        const int g = nt >> 1, hi = nt & 1;
                        mma_bf16(acc[mt][nt], af[ks][mt], bf[ks][g][hi], bf[ks][g][hi + 2]);
                    }
        }

        // ---- epilogue: scale, mask, label, online LSE (registers only) ----
        #pragma unroll
        for (int mt = 0; mt < 2; ++mt)
            #pragma unroll
            for (int rh = 0; rh < 2; ++rh) {
                const int i = i_base + mt * 16 + rh * 8;
                float v[8];
                float mx = -INFINITY;
                #pragma unroll
                for (int nt = 0; nt < 4; ++nt)
                    #pragma unroll
                    for (int cp = 0; cp < 2; ++cp) {
                        const int j = j0 + jcol_base + nt * 8 + cp;
                        float f = acc[mt][nt][rh * 2 + cp] * INV_T;
                        if (j == i) f -= DIAG_SUB;
                        if (j == (i ^ 1)) g_t[i] = f;
                        v[nt * 2 + cp] = f;
                        mx = fmaxf(mx, f);
                    }
                const float nm = fmaxf(rm[mt][rh], mx);
                float s = 0.0f;
                #pragma unroll
                for (int q = 0; q < 8; ++q) s += __expf(v[q] - nm);
                rs[mt][rh] = rs[mt][rh] * __expf(rm[mt][rh] - nm) + s;
                rm[mt][rh] = nm;
            }
    }

    // ---- merge (m,s): lanes sharing a row, then the 4 warp-columns ----
    CP_WAIT(0);
    __syncthreads();                       // smem reusable
    float* bufm = (float*)smem;            // [4][BM]
    float* bufs = bufm + 4 * BM;           // [4][BM]

    #pragma unroll
    for (int mt = 0; mt < 2; ++mt)
        #pragma unroll
        for (int rh = 0; rh < 2; ++rh) {
            float m = rm[mt][rh], s = rs[mt][rh];
            #pragma unroll
            for (int off = 1; off <= 2; off <<= 1) {
                float mo = __shfl_xor_sync(0xffffffffu, m, off);
                float so = __shfl_xor_sync(0xffffffffu, s, off);
                float mn = fmaxf(m, mo);
                s = s * __expf(m - mn) + so * __expf(mo - mn);
                m = mn;
            }
            if ((lane & 3) == 0) {
                const int rl = wm * 32 + (lane >> 2) + mt * 16 + rh * 8;
                bufm[wn * BM + rl] = m;
                bufs[wn * BM + rl] = s;
            }
        }
    __syncthreads();

    if (tid < BM) {
        float M = -INFINITY;
        #pragma unroll
        for (int q = 0; q < 4; ++q) M = fmaxf(M, bufm[q * BM + tid]);
        float S = 0.0f;
        #pragma unroll
        for (int q = 0; q < 4; ++q) S += bufs[q * BM + tid] * __expf(bufm[q * BM + tid] - M);
        g_mpart[split][r0 + tid] = M;
        g_spart[split][r0 + tid] = S;
    }
}

// ---------------------------------------------------------------------------
// Kernel 3: merge splits per row, per-block deterministic partial sums
// ---------------------------------------------------------------------------
__global__ void reduce_rows_kernel() {
    const int row = blockIdx.x * 256 + threadIdx.x;
    __shared__ float red[8];

    float M = -INFINITY;
    #pragma unroll
    for (int s = 0; s < SPLIT; ++s) M = fmaxf(M, g_mpart[s][row]);
    float S = 0.0f;
    #pragma unroll
    for (int s = 0; s < SPLIT; ++s) S += g_spart[s][row] * __expf(g_mpart[s][row] - M);
    float li = (M + logf(S)) - g_t[row];

    #pragma unroll
    for (int o = 16; o; o >>= 1) li += __shfl_down_sync(0xffffffffu, li, o);
    if ((threadIdx.x & 31) == 0) red[threadIdx.x >> 5] = li;
    __syncthreads();
    if (threadIdx.x < 8) {
        float v = red[threadIdx.x];
        #pragma unroll
        for (int o = 4; o; o >>= 1) v += __shfl_down_sync(0xffu, v, o);
        if (threadIdx.x == 0) g_partial[blockIdx.x] = v;
    }
}

// ---------------------------------------------------------------------------
// Kernel 4: final deterministic sum -> mean
// ---------------------------------------------------------------------------
__global__ void final_kernel(float* __restrict__ out) {
    float v = g_partial[threadIdx.x];
    #pragma unroll
    for (int o = 16; o; o >>= 1) v += __shfl_down_sync(0xffffffffu, v, o);
    if (threadIdx.x == 0) out[0] = v * (1.0f / (float)N);
}

extern "C" void kernel_launch(void* const* d_in, const int* in_sizes, int n_in,
                              void* d_out, int out_size) {
    const float* x = (const float*)d_in[0];
    float* out = (float*)d_out;

    cudaFuncSetAttribute(simloss_kernel,
                         cudaFuncAttributeMaxDynamicSharedMemorySize, SMEM_DYN);

    normalize_kernel<<<N, 256>>>(x);
    dim3 grid(N / BM, SPLIT);
    simloss_kernel<<<grid, 512, SMEM_DYN>>>();
    reduce_rows_kernel<<<RED_BLOCKS, 256>>>();
    final_kernel<<<1, 32>>>(out);
}